// round 3
// baseline (speedup 1.0000x reference)
#include <cuda_runtime.h>
#include <cuda_bf16.h>

// Problem constants
#define B_   256
#define S_   2048
#define VOCAB_ 10
#define E_   32
#define H_   64
#define OUT_ 10

#define NTAB (VOCAB_ * VOCAB_)   // 100 table rows
#define CHUNK 16                  // steps buffered before logits flush
#define NCHUNK (S_ / CHUNK)       // 128
#define HS2 72                    // padded/skewed row stride (floats)

// Scratch (no cudaMalloc allowed)
__device__ __align__(16) float g_table[NTAB * H_];     // 25.6 KB
__device__ __align__(16) unsigned char g_idx[B_ * S_]; // 512 KB

// ---------------------------------------------------------------------------
// Fast accurate-enough tanh: abs err ~5e-7, ~7 instrs, 2 MUFU.
// ---------------------------------------------------------------------------
__device__ __forceinline__ float fast_tanh(float x) {
    x = fminf(fmaxf(x, -15.0f), 15.0f);
    float e = __expf(2.0f * x);                 // FMUL + MUFU.EX2
    return __fdividef(e - 1.0f, e + 1.0f);      // MUFU.RCP + FMUL
}

// ---------------------------------------------------------------------------
// Prep kernel (merged): blocks [0,25) build the 100x64 table,
// blocks [25, 25+2048) compact (num1,num2) -> uint8 index.
// ---------------------------------------------------------------------------
#define TAB_BLOCKS 25
__global__ void prep_kernel(const int* __restrict__ num1,
                            const int* __restrict__ num2,
                            const float* __restrict__ embed,
                            const float* __restrict__ Wx,
                            const float* __restrict__ bvec) {
    if (blockIdx.x < TAB_BLOCKS) {
        int i = blockIdx.x * 256 + threadIdx.x;    // 0..6399
        if (i < NTAB * H_) {
            int v = i >> 6, j = i & 63;
            int v1 = v / VOCAB_, v2 = v % VOCAB_;
            float acc = bvec[j];
            #pragma unroll
            for (int e = 0; e < E_; ++e) {
                acc = fmaf(embed[v1 * E_ + e], Wx[e * H_ + j], acc);
                acc = fmaf(embed[v2 * E_ + e], Wx[(E_ + e) * H_ + j], acc);
            }
            g_table[i] = acc;
        }
    } else {
        int i = (blockIdx.x - TAB_BLOCKS) * 256 + threadIdx.x;
        if (i < B_ * S_) {
            g_idx[i] = (unsigned char)(num1[i] * VOCAB_ + num2[i]);
        }
    }
}

// ---------------------------------------------------------------------------
// RNN kernel: one chain per 128-thread CTA, grid = 256 (single wave, occ 2).
// Lane pair (2m, 2m+1) of warp w computes h_j, j = 16w + m:
//   half 0 accumulates k in [0,32), half 1 k in [32,64); shfl_xor(1) combines.
// h stored skewed: col(j) = j + 4*(j>=32) so the two halves' broadcast
// reads hit disjoint banks.
// ---------------------------------------------------------------------------
__global__ void __launch_bounds__(128, 2)
rnn_kernel(const float* __restrict__ Wh,
           const float* __restrict__ Wd,
           const float* __restrict__ bd,
           float* __restrict__ out) {
    __shared__ __align__(16) float T_sh[NTAB * H_];      // 25600 B
    __shared__ __align__(16) float Wd_sh[H_ * OUT_];     // 2560 B
    __shared__ float bd_sh[OUT_];
    __shared__ __align__(16) float hbuf[CHUNK * HS2];    // 4608 B
    __shared__ __align__(16) unsigned char idxb[2][CHUNK];

    const int tid  = threadIdx.x;
    const int w    = tid >> 5;
    const int lane = tid & 31;
    const int m    = lane >> 1;
    const int half = lane & 1;
    const int j    = (w << 4) + m;          // h index this pair owns
    const int colj = j + ((j >> 5) << 2);   // skewed column for h_j
    const int b    = blockIdx.x;

    // cooperative loads
    for (int i = tid; i < NTAB * H_; i += 128) T_sh[i] = g_table[i];
    for (int i = tid; i < H_ * OUT_; i += 128) Wd_sh[i] = Wd[i];
    if (tid < OUT_) bd_sh[tid] = bd[tid];

    // Wh slice for this thread: rows [32*half, 32*half+32), column j
    float wh[32];
    #pragma unroll
    for (int kk = 0; kk < 32; ++kk) wh[kk] = Wh[(half * 32 + kk) * H_ + j];

    // h_{-1} = 0 lives in ring row CHUNK-1
    if (tid < H_) {
        int c0 = tid + ((tid >> 5) << 2);
        hbuf[(CHUNK - 1) * HS2 + c0] = 0.0f;
    }

    const unsigned char* idx_g = &g_idx[(size_t)b * S_];
    if (tid == 0) {
        *reinterpret_cast<int4*>(&idxb[0][0]) =
            *reinterpret_cast<const int4*>(idx_g);
    }
    __syncthreads();

    int4 nextidx;

    for (int c = 0; c < NCHUNK; ++c) {
        if (tid == 0 && c + 1 < NCHUNK) {
            nextidx = *reinterpret_cast<const int4*>(idx_g + (c + 1) * CHUNK);
        }
        const unsigned char* ib = &idxb[c & 1][0];

        #pragma unroll 1
        for (int t = 0; t < CHUNK; ++t) {
            const int cur  = t;
            const int prev = (t + CHUNK - 1) & (CHUNK - 1);
            const int idx  = (int)ib[t];

            // this half's 32 h_prev values (uniform per half -> broadcast)
            const float4* hp4 = reinterpret_cast<const float4*>(
                &hbuf[prev * HS2 + 36 * half]);

            float a0 = half ? 0.0f : T_sh[idx * H_ + j];
            float a1 = 0.0f, a2 = 0.0f, a3 = 0.0f;
            #pragma unroll
            for (int k4 = 0; k4 < 8; ++k4) {
                float4 hv = hp4[k4];
                a0 = fmaf(hv.x, wh[4 * k4 + 0], a0);
                a1 = fmaf(hv.y, wh[4 * k4 + 1], a1);
                a2 = fmaf(hv.z, wh[4 * k4 + 2], a2);
                a3 = fmaf(hv.w, wh[4 * k4 + 3], a3);
            }
            float p = (a0 + a1) + (a2 + a3);
            p += __shfl_xor_sync(0xffffffffu, p, 1);
            float hj = fast_tanh(p);
            if (half == 0) hbuf[cur * HS2 + colj] = hj;
            __syncthreads();
        }

        // logits for this chunk: [16,64] @ [64,10] + bd  (160 outputs)
        const int s0 = c * CHUNK;
        for (int i = tid; i < CHUNK * OUT_; i += 128) {
            const int t = i / OUT_;
            const int o = i - t * OUT_;
            const float* hr = &hbuf[t * HS2];
            float acc0 = bd_sh[o], acc1 = 0.0f;
            #pragma unroll
            for (int k = 0; k < 32; k += 2) {
                acc0 = fmaf(hr[k],     Wd_sh[k * OUT_ + o],       acc0);
                acc1 = fmaf(hr[k + 1], Wd_sh[(k + 1) * OUT_ + o], acc1);
            }
            #pragma unroll
            for (int k = 32; k < 64; k += 2) {
                acc0 = fmaf(hr[k + 4], Wd_sh[k * OUT_ + o],       acc0);
                acc1 = fmaf(hr[k + 5], Wd_sh[(k + 1) * OUT_ + o], acc1);
            }
            out[((size_t)b * S_ + (s0 + t)) * OUT_ + o] = acc0 + acc1;
        }

        // publish next chunk's indices; barrier covers hbuf reuse + idx
        if (tid == 0 && c + 1 < NCHUNK) {
            *reinterpret_cast<int4*>(&idxb[(c + 1) & 1][0]) = nextidx;
        }
        __syncthreads();
    }
}

// ---------------------------------------------------------------------------
// Entry point
// Inputs: num1[i32 B*S], num2[i32 B*S], embed[f32 10*32], Wx[f32 64*64],
//         Wh[f32 64*64], b[f32 64], Wd[f32 64*10], bd[f32 10]
// Output: float32 [B, S, 10]
// ---------------------------------------------------------------------------
extern "C" void kernel_launch(void* const* d_in, const int* in_sizes, int n_in,
                              void* d_out, int out_size) {
    const int*   num1  = (const int*)d_in[0];
    const int*   num2  = (const int*)d_in[1];
    const float* embed = (const float*)d_in[2];
    const float* Wx    = (const float*)d_in[3];
    const float* Wh    = (const float*)d_in[4];
    const float* bvec  = (const float*)d_in[5];
    const float* Wd    = (const float*)d_in[6];
    const float* bd    = (const float*)d_in[7];
    float* out = (float*)d_out;

    const int idx_blocks = (B_ * S_ + 255) / 256;
    prep_kernel<<<TAB_BLOCKS + idx_blocks, 256>>>(num1, num2, embed, Wx, bvec);

    rnn_kernel<<<B_, 128>>>(Wh, Wd, bd, out);
}

// round 5
// speedup vs baseline: 1.4890x; 1.4890x over previous
#include <cuda_runtime.h>
#include <cuda_bf16.h>

// Problem constants
#define B_   256
#define S_   2048
#define VOCAB_ 10
#define E_   32
#define H_   64
#define OUT_ 10

#define NTAB (VOCAB_ * VOCAB_)   // 100 table rows
#define CHUNK 16                  // steps per logits flush
#define NCHUNK (S_ / CHUNK)       // 128
#define HCS 68                    // hc row stride in floats (16B-aligned)

typedef unsigned long long ull;

// Scratch (no cudaMalloc allowed)
__device__ __align__(16) float g_table[NTAB * H_];     // 25.6 KB
__device__ __align__(16) unsigned char g_idx[B_ * S_]; // 512 KB

// ---- packed f32x2 helpers -------------------------------------------------
__device__ __forceinline__ void fma2(ull& acc, ull a, ull b) {
    asm("fma.rn.f32x2 %0, %1, %2, %3;" : "=l"(acc) : "l"(a), "l"(b), "l"(acc));
}
__device__ __forceinline__ ull add2(ull a, ull b) {
    ull r; asm("add.rn.f32x2 %0, %1, %2;" : "=l"(r) : "l"(a), "l"(b)); return r;
}
__device__ __forceinline__ ull pack2(float lo, float hi) {
    ull r;
    asm("mov.b64 %0, {%1, %2};" : "=l"(r)
        : "r"(__float_as_uint(lo)), "r"(__float_as_uint(hi)));
    return r;
}
__device__ __forceinline__ void unpack2(ull v, float& lo, float& hi) {
    unsigned int a, b;
    asm("mov.b64 {%0, %1}, %2;" : "=r"(a), "=r"(b) : "l"(v));
    lo = __uint_as_float(a); hi = __uint_as_float(b);
}

// Fast tanh: abs err ~5e-7 (validated R3: final rel_err 6.3e-6)
__device__ __forceinline__ float fast_tanh(float x) {
    x = fminf(fmaxf(x, -15.0f), 15.0f);
    float e = __expf(2.0f * x);
    return __fdividef(e - 1.0f, e + 1.0f);
}

// ---------------------------------------------------------------------------
// Prep kernel: blocks [0,25) build table, rest compact indices.
// ---------------------------------------------------------------------------
#define TAB_BLOCKS 25
__global__ void prep_kernel(const int* __restrict__ num1,
                            const int* __restrict__ num2,
                            const float* __restrict__ embed,
                            const float* __restrict__ Wx,
                            const float* __restrict__ bvec) {
    if (blockIdx.x < TAB_BLOCKS) {
        int i = blockIdx.x * 256 + threadIdx.x;
        if (i < NTAB * H_) {
            int v = i >> 6, j = i & 63;
            int v1 = v / VOCAB_, v2 = v % VOCAB_;
            float acc = bvec[j];
            #pragma unroll
            for (int e = 0; e < E_; ++e) {
                acc = fmaf(embed[v1 * E_ + e], Wx[e * H_ + j], acc);
                acc = fmaf(embed[v2 * E_ + e], Wx[(E_ + e) * H_ + j], acc);
            }
            g_table[i] = acc;
        }
    } else {
        int i = (blockIdx.x - TAB_BLOCKS) * 256 + threadIdx.x;
        if (i < B_ * S_) {
            g_idx[i] = (unsigned char)(num1[i] * VOCAB_ + num2[i]);
        }
    }
}

// ---------------------------------------------------------------------------
// RNN kernel: one chain per 64-thread CTA (2 warps). Thread j owns h_j.
// Per step: h_prev read as 16 broadcast LDS.128 halves (packed k-pairs),
// 32 x fma.rn.f32x2 with register-resident packed Wh column, horizontal add,
// + T[idx][j], fast_tanh, STS.32, one 64-thread barrier.
// h history ring hc[16][HCS] doubles as the logits source; flush every 16.
// ---------------------------------------------------------------------------
__global__ void __launch_bounds__(64, 2)
rnn_kernel(const float* __restrict__ Wh,
           const float* __restrict__ Wd,
           const float* __restrict__ bd,
           float* __restrict__ out) {
    __shared__ __align__(16) float T_sh[NTAB * H_];   // 25600 B
    __shared__ __align__(16) float hc[CHUNK * HCS];   // 4352 B history ring
    __shared__ __align__(16) ull  Wdp[OUT_ * 32];     // 2560 B packed Wd cols
    __shared__ float bd_sh[OUT_];

    const int tid = threadIdx.x;   // 0..63 = output index j
    const int b   = blockIdx.x;

    // cooperative smem fills
    for (int i = tid; i < NTAB * H_; i += 64) T_sh[i] = g_table[i];
    for (int i = tid; i < OUT_ * 32; i += 64) {
        int o = i >> 5, k2 = i & 31;
        Wdp[i] = pack2(Wd[(2 * k2) * OUT_ + o], Wd[(2 * k2 + 1) * OUT_ + o]);
    }
    if (tid < OUT_) bd_sh[tid] = bd[tid];

    // packed Wh column j: wkp[i] = (Wh[2i][j], Wh[2i+1][j])
    ull wkp[32];
    #pragma unroll
    for (int i = 0; i < 32; ++i) {
        wkp[i] = pack2(Wh[(2 * i) * H_ + tid], Wh[(2 * i + 1) * H_ + tid]);
    }

    // h_{-1} = 0 in ring row CHUNK-1
    hc[(CHUNK - 1) * HCS + tid] = 0.0f;

    const unsigned char* idx_g = &g_idx[(size_t)b * S_];
    int4 curidx = *reinterpret_cast<const int4*>(idx_g);
    __syncthreads();

    for (int c = 0; c < NCHUNK; ++c) {
        int4 nextidx;
        if (c + 1 < NCHUNK) {
            nextidx = *reinterpret_cast<const int4*>(idx_g + (c + 1) * CHUNK);
        }
        const unsigned int packs[4] = {
            (unsigned int)curidx.x, (unsigned int)curidx.y,
            (unsigned int)curidx.z, (unsigned int)curidx.w };

        #pragma unroll
        for (int t = 0; t < CHUNK; ++t) {
            const int prev = (t + CHUNK - 1) & (CHUNK - 1);
            const int idx  = (int)((packs[t >> 2] >> ((t & 3) * 8)) & 255u);

            // T contribution (issued early, scalar)
            float tv = T_sh[idx * H_ + tid];

            // hp[g] covers h floats [4g, 4g+4) = packed pairs 2g, 2g+1
            const ulonglong2* hp =
                reinterpret_cast<const ulonglong2*>(&hc[prev * HCS]);
            ull a0 = 0, a1 = 0, a2 = 0, a3 = 0;
            #pragma unroll
            for (int g = 0; g < 16; g += 2) {
                ulonglong2 hv0 = hp[g];
                ulonglong2 hv1 = hp[g + 1];
                fma2(a0, hv0.x, wkp[2 * g + 0]);
                fma2(a1, hv0.y, wkp[2 * g + 1]);
                fma2(a2, hv1.x, wkp[2 * g + 2]);
                fma2(a3, hv1.y, wkp[2 * g + 3]);
            }
            ull s = add2(add2(a0, a1), add2(a2, a3));
            float lo, hi; unpack2(s, lo, hi);
            float hj = fast_tanh(tv + lo + hi);
            hc[t * HCS + tid] = hj;
            __syncthreads();
        }

        // ---- logits flush: 160 outputs, packed over k ----
        const int s0 = c * CHUNK;
        #pragma unroll
        for (int r = 0; r < 3; ++r) {
            int i = tid + r * 64;
            if (i < CHUNK * OUT_) {
                int t = i & 15, o = i >> 4;
                const ulonglong2* hp =
                    reinterpret_cast<const ulonglong2*>(&hc[t * HCS]);
                const ulonglong2* wp =
                    reinterpret_cast<const ulonglong2*>(&Wdp[o * 32]);
                ull a0 = 0, a1 = 0;
                #pragma unroll
                for (int g = 0; g < 16; ++g) {
                    ulonglong2 hv = hp[g];
                    ulonglong2 wv = wp[g];
                    fma2(a0, hv.x, wv.x);
                    fma2(a1, hv.y, wv.y);
                }
                float lo, hi; unpack2(add2(a0, a1), lo, hi);
                out[((size_t)b * S_ + (s0 + t)) * OUT_ + o] =
                    bd_sh[o] + lo + hi;
            }
        }
        curidx = nextidx;
        __syncthreads();
    }
}

// ---------------------------------------------------------------------------
// Entry point
// Inputs: num1[i32 B*S], num2[i32 B*S], embed[f32 10*32], Wx[f32 64*64],
//         Wh[f32 64*64], b[f32 64], Wd[f32 64*10], bd[f32 10]
// Output: float32 [B, S, 10]
// ---------------------------------------------------------------------------
extern "C" void kernel_launch(void* const* d_in, const int* in_sizes, int n_in,
                              void* d_out, int out_size) {
    const int*   num1  = (const int*)d_in[0];
    const int*   num2  = (const int*)d_in[1];
    const float* embed = (const float*)d_in[2];
    const float* Wx    = (const float*)d_in[3];
    const float* Wh    = (const float*)d_in[4];
    const float* bvec  = (const float*)d_in[5];
    const float* Wd    = (const float*)d_in[6];
    const float* bd    = (const float*)d_in[7];
    float* out = (float*)d_out;

    const int idx_blocks = (B_ * S_ + 255) / 256;
    prep_kernel<<<TAB_BLOCKS + idx_blocks, 256>>>(num1, num2, embed, Wx, bvec);

    rnn_kernel<<<B_, 64>>>(Wh, Wd, bd, out);
}